// round 6
// baseline (speedup 1.0000x reference)
#include <cuda_runtime.h>
#include <cstdint>
#include <cstddef>

#define CH   40
#define TT   2000
#define LL   256
#define NB   64
#define NEGF (-1.0e30f)
#define POSF (1.0e30f)
#define LOG2E 1.4426950408889634f
#define LN2   0.6931471805599453f

// lg2(1+u) ~ poly(x), x = u-1, u in [0,2]
#define D0 0.999835f
#define D1 0.721619f
#define D2 (-0.177414f)
#define D3 0.058070f
#define D4 (-0.029748f)
#define D5 0.0127536f

// ---------------- device scratch ----------------
__device__ unsigned long long g_maskkeys[NB * 256];
__device__ int   g_labels[NB * 256];
__device__ int   g_tlen[NB];
__device__ float g_em[(size_t)NB * TT * 256];
__device__ float g_loss[NB];
__device__ unsigned int g_done;

// ---------------- PTX helpers ----------------
__device__ __forceinline__ float ex2f(float x) {
    float r; asm("ex2.approx.ftz.f32 %0, %1;" : "=f"(r) : "f"(x)); return r;
}
__device__ __forceinline__ float lg2f(float x) {
    float r; asm("lg2.approx.ftz.f32 %0, %1;" : "=f"(r) : "f"(x)); return r;
}
__device__ __forceinline__ unsigned long long pk2(float x, float y) {
    unsigned long long r;
    asm("mov.b64 %0, {%1, %2};" : "=l"(r) : "f"(x), "f"(y));
    return r;
}
__device__ __forceinline__ void ffma2(unsigned long long &a, unsigned long long m, unsigned long long d) {
    asm("fma.rn.f32x2 %0, %1, %2, %3;" : "=l"(a) : "l"(m), "l"(d), "l"(a));
}
__device__ __forceinline__ void up2(unsigned long long v, float &x, float &y) {
    asm("mov.b64 {%0, %1}, %2;" : "=f"(x), "=f"(y) : "l"(v));
}

// =====================================================================
// Kernel 1: preprocessing (verified exact)
// =====================================================================
__global__ void k_preprocess(const int* __restrict__ targets) {
    const int n = blockIdx.x;
    const int l = threadIdx.x;

    __shared__ unsigned long long skey[256];
    __shared__ int sscan[256];
    __shared__ int sinv[256];

    if (n == 0 && l == 0) g_done = 0;

    unsigned long long key = 0ull;
#pragma unroll
    for (int c = 0; c < CH; c++) {
        key |= ((unsigned long long)(targets[(n * CH + c) * LL + l] & 1)) << (CH - 1 - c);
    }
    skey[l] = (key << 8) | (unsigned long long)l;
    __syncthreads();

    for (int k = 2; k <= 256; k <<= 1) {
        for (int j = k >> 1; j > 0; j >>= 1) {
            int ixj = l ^ j;
            if (ixj > l) {
                unsigned long long a = skey[l], b = skey[ixj];
                bool up = ((l & k) == 0);
                if ((a > b) == up) { skey[l] = b; skey[ixj] = a; }
            }
            __syncthreads();
        }
    }

    unsigned long long kv = skey[l] >> 8;
    unsigned long long kvp = (l > 0) ? (skey[l - 1] >> 8) : 0ull;
    int head = (l == 0 || kv != kvp) ? 1 : 0;
    sscan[l] = head;
    __syncthreads();
    for (int off = 1; off < 256; off <<= 1) {
        int v = sscan[l];
        int w = (l >= off) ? sscan[l - off] : 0;
        __syncthreads();
        sscan[l] = v + w;
        __syncthreads();
    }
    const int u   = sscan[255];
    const int uid = sscan[l] - 1;
    const int orig = (int)(skey[l] & 255ull);
    int inv2 = uid + 1; if (inv2 == u) inv2 = 0;
    sinv[orig] = inv2;
    if (head) g_maskkeys[n * 256 + inv2] = kv;
    __syncthreads();

    int flag = (l > 0 && sinv[l] != sinv[l - 1]) ? 1 : 0;
    int myinv = sinv[l];
    sscan[l] = flag;
    __syncthreads();
    for (int off = 1; off < 256; off <<= 1) {
        int v = sscan[l];
        int w = (l >= off) ? sscan[l - off] : 0;
        __syncthreads();
        sscan[l] = v + w;
        __syncthreads();
    }
    if (flag) g_labels[n * 256 + (sscan[l] - 1)] = myinv;
    if (l == 0) g_tlen[n] = sscan[255];
}

// =====================================================================
// Kernel 2: emission table (verified exact)
// =====================================================================
__global__ void __launch_bounds__(128) k_emission(const float* __restrict__ lp) {
    const int n = blockIdx.y;
    const int t = blockIdx.x * 128 + threadIdx.x;

    __shared__ float maskf[CH * 256];
    for (int idx = threadIdx.x; idx < CH * 256; idx += 128) {
        int c = idx >> 8, j = idx & 255;
        unsigned long long mk = g_maskkeys[n * 256 + j];
        maskf[idx] = (float)((mk >> (CH - 1 - c)) & 1ull);
    }
    __syncthreads();
    if (t >= TT) return;

    const float* lp0 = lp + ((size_t)n * 2 + 0) * CH * TT;
    const float* lp1 = lp + ((size_t)n * 2 + 1) * CH * TT;

    unsigned long long d2[CH];
    float base = 0.0f;
    float blank = 0.0f;
#pragma unroll
    for (int c = 0; c < CH; c++) {
        float x0 = __ldg(lp0 + c * TT + t);
        float x1 = __ldg(lp1 + c * TT + t);
        if (c == 0) blank = x1;
        float dd = x1 - x0;
        base += x0;
        d2[c] = pk2(dd, dd);
    }

    float* out = g_em + ((size_t)n * TT + t) * 256;
    out[0] = blank * LOG2E;

    const unsigned long long b2 = pk2(base, base);
    for (int j8 = 0; j8 < 32; j8++) {
        unsigned long long acc0 = b2, acc1 = b2, acc2 = b2, acc3 = b2;
#pragma unroll
        for (int c = 0; c < CH; c++) {
            const float4* mp = (const float4*)(maskf + c * 256 + j8 * 8);
            float4 f0 = mp[0];
            float4 f1 = mp[1];
            ffma2(acc0, pk2(f0.x, f0.y), d2[c]);
            ffma2(acc1, pk2(f0.z, f0.w), d2[c]);
            ffma2(acc2, pk2(f1.x, f1.y), d2[c]);
            ffma2(acc3, pk2(f1.z, f1.w), d2[c]);
        }
        float vx, vy;
        int j = j8 * 8;
        up2(acc0, vx, vy);
        if (j > 0) out[j] = vx * LOG2E;
        out[j + 1] = vy * LOG2E;
        up2(acc1, vx, vy);
        out[j + 2] = vx * LOG2E; out[j + 3] = vy * LOG2E;
        up2(acc2, vx, vy);
        out[j + 4] = vx * LOG2E; out[j + 5] = vy * LOG2E;
        up2(acc3, vx, vy);
        out[j + 6] = vx * LOG2E; out[j + 7] = vy * LOG2E;
    }
}

// =====================================================================
// Kernel 3: CTC forward — halo wavefront. Branch-free steps, pure
// register state, hoisted emission loads, boundary-only exchange with
// one barrier per 8-step window. Fused final mean.
// =====================================================================
__device__ __forceinline__ void stage_rows(float (*sEm)[256], const float* emn,
                                           int r0, int tid) {
    if (tid < 256) {
#pragma unroll
        for (int q = 0; q < 2; q++) {
            int c = tid * 2 + q;
            int r = r0 + (c >> 6);
            int off = (c & 63) * 4;
            if (r < TT) {
                uint32_t dst = (uint32_t)__cvta_generic_to_shared(&sEm[r & 31][off]);
                const float* src = emn + (size_t)r * 256 + off;
                asm volatile("cp.async.cg.shared.global [%0], [%1], 16;\n"
                             :: "r"(dst), "l"(src));
            }
        }
    }
    asm volatile("cp.async.commit_group;\n" ::: "memory");
}

__device__ __forceinline__ float lg2_poly(float u) {   // lg2(1+u), u in [0,2]
    float x = u - 1.0f;
    float x2 = x * x;
    float p = fmaf(D5, x, D4);
    float q = fmaf(D3, x, D2);
    float r = fmaf(D1, x, D0);
    p = fmaf(p, x2, q);
    return fmaf(p, x2, r);
}

__global__ void __launch_bounds__(352) k_ctc(float* __restrict__ d_out) {
    const int n = blockIdx.x;
    const int tid = threadIdx.x;
    const int w = tid >> 5;
    const int l = tid & 31;
    const int kp = 24 * w + l;

    __shared__ __align__(16) float sEm[32][256];     // emission ring
    __shared__ __align__(8)  float2 EX[2][11][8];    // boundary exchange
    __shared__ __align__(8)  float2 AF[288];         // final alphas

    const int tlen = g_tlen[n];
    const float* emn = g_em + (size_t)n * TT * 256;

    int labO = 0; bool skip = false;
    if (kp < tlen) {
        labO = g_labels[n * 256 + kp];
        if (kp >= 1) {
            int lm2 = g_labels[n * 256 + kp - 1];
            skip = (labO != 0) && (labO != lm2);
        }
    }
    // branch-free selectors
    const float edgeSel = (tid == 0) ? NEGF : POSF;
    const float skipSel = (skip && tid != 0) ? POSF : NEGF;

    stage_rows(sEm, emn, 1, tid);
    stage_rows(sEm, emn, 9, tid);

    // t = 0 init (register state; kp==0 lane gets real values)
    float aE = NEGF, aO = NEGF;
    if (kp == 0) {
        int lab0 = (tlen > 0) ? g_labels[n * 256] : 0;
        aE = __ldg(emn + 0);
        aO = __ldg(emn + lab0);
    }

    int buf = 0;

#define DO_STEP(s)                                                          \
    do {                                                                    \
        float aOprev = __shfl_up_sync(0xffffffffu, aO, 1);                  \
        float aOp = fminf(aOprev, edgeSel);                                 \
        float cc  = fminf(aOprev, skipSel);                                 \
        float mE = fmaxf(aE, aOp);                                          \
        float dE = fminf(aE, aOp) - mE;                                     \
        float hi = fmaxf(aO, aE), lo2 = fminf(aO, aE);                      \
        float mO  = fmaxf(hi, cc);                                          \
        float sec = fminf(hi, fmaxf(lo2, cc)) - mO;                         \
        float th  = fminf(lo2, cc) - mO;                                    \
        float uE = ex2f(dE);                                                \
        float uO = ex2f(sec) + ex2f(th);                                    \
        aE = (mE + emEr[s]) + lg2_poly(uE);                                 \
        aO = (mO + emOr[s]) + lg2_poly(uO);                                 \
    } while (0)

    for (int b = 0; b < 249; b++) {
        stage_rows(sEm, emn, 8 * b + 17, tid);
        asm volatile("cp.async.wait_group 2;\n" ::: "memory");
        // publish boundary (top 8 lanes), sync, refresh invalid lanes
        if (l >= 24) EX[buf][w][l - 24] = make_float2(aE, aO);
        __syncthreads();
        if (w > 0 && l < 8) {
            float2 v = EX[buf][w - 1][l];
            aE = v.x; aO = v.y;
        }
        buf ^= 1;

        // hoist emission loads for the window
        const int t0 = 8 * b + 1;
        float emEr[8], emOr[8];
#pragma unroll
        for (int s = 0; s < 8; s++) {
            const float* srow = &sEm[(t0 + s) & 31][0];
            emEr[s] = srow[0];
            emOr[s] = srow[labO];
        }
#pragma unroll
        for (int s = 0; s < 8; s++) DO_STEP(s);
    }

    // tail window: t = 1993..1999 (7 steps)
    {
        asm volatile("cp.async.wait_group 0;\n" ::: "memory");
        if (l >= 24) EX[buf][w][l - 24] = make_float2(aE, aO);
        __syncthreads();
        if (w > 0 && l < 8) {
            float2 v = EX[buf][w - 1][l];
            aE = v.x; aO = v.y;
        }
        float emEr[8], emOr[8];
#pragma unroll
        for (int s = 0; s < 7; s++) {
            const float* srow = &sEm[(1993 + s) & 31][0];
            emEr[s] = srow[0];
            emOr[s] = srow[labO];
        }
#pragma unroll
        for (int s = 0; s < 7; s++) DO_STEP(s);
    }
#undef DO_STEP

    // collect final alphas (valid lanes: warp0 all; others l >= 7)
    if (w == 0 || l >= 7) AF[kp] = make_float2(aE, aO);
    __syncthreads();

    if (tid == 0) {
        float ea = AF[tlen].x;                          // alpha[2*tlen]
        float eb = AF[(tlen >= 1) ? tlen - 1 : 0].y;    // alpha[2*tlen-1]
        float m = fmaxf(ea, eb);
        float l2 = m + lg2f(ex2f(ea - m) + ex2f(eb - m));
        g_loss[n] = -l2 * LN2;
        __threadfence();
        unsigned int tk = atomicAdd(&g_done, 1u);
        if (tk == NB - 1) {
            volatile float* gl = g_loss;
            float s = 0.0f;
            for (int i = 0; i < NB; i++) s += gl[i];
            d_out[0] = s * (1.0f / (float)NB);
        }
    }
}

// =====================================================================
extern "C" void kernel_launch(void* const* d_in, const int* in_sizes, int n_in,
                              void* d_out, int out_size) {
    const float* lp = (const float*)d_in[0];
    const int*   tg = (const int*)d_in[1];
    if (n_in >= 2 && in_sizes[0] == NB * CH * LL) {
        lp = (const float*)d_in[1];
        tg = (const int*)d_in[0];
    }

    k_preprocess<<<NB, 256>>>(tg);
    dim3 g2((TT + 127) / 128, NB);
    k_emission<<<g2, 128>>>(lp);
    k_ctc<<<NB, 352>>>((float*)d_out);
}

// round 7
// speedup vs baseline: 1.0461x; 1.0461x over previous
#include <cuda_runtime.h>
#include <cstdint>
#include <cstddef>

#define CH   40
#define TT   2000
#define LL   256
#define NB   64
#define NEGF (-1.0e30f)
#define POSF (1.0e30f)
#define LOG2E 1.4426950408889634f
#define LN2   0.6931471805599453f

// ---------------- device scratch ----------------
__device__ unsigned long long g_maskkeys[NB * 256];
__device__ int   g_labels[NB * 256];
__device__ int   g_tlen[NB];
__device__ float g_em[(size_t)NB * TT * 256];
__device__ float g_loss[NB];
__device__ unsigned int g_done;

// ---------------- PTX helpers ----------------
__device__ __forceinline__ float ex2f(float x) {
    float r; asm("ex2.approx.ftz.f32 %0, %1;" : "=f"(r) : "f"(x)); return r;
}
__device__ __forceinline__ float lg2f(float x) {
    float r; asm("lg2.approx.ftz.f32 %0, %1;" : "=f"(r) : "f"(x)); return r;
}
__device__ __forceinline__ unsigned long long pk2(float x, float y) {
    unsigned long long r;
    asm("mov.b64 %0, {%1, %2};" : "=l"(r) : "f"(x), "f"(y));
    return r;
}
__device__ __forceinline__ void ffma2(unsigned long long &a, unsigned long long m, unsigned long long d) {
    asm("fma.rn.f32x2 %0, %1, %2, %3;" : "=l"(a) : "l"(m), "l"(d), "l"(a));
}
__device__ __forceinline__ void up2(unsigned long long v, float &x, float &y) {
    asm("mov.b64 {%0, %1}, %2;" : "=f"(x), "=f"(y) : "l"(v));
}

// =====================================================================
// Kernel 1: preprocessing (verified exact)
// =====================================================================
__global__ void k_preprocess(const int* __restrict__ targets) {
    const int n = blockIdx.x;
    const int l = threadIdx.x;

    __shared__ unsigned long long skey[256];
    __shared__ int sscan[256];
    __shared__ int sinv[256];

    if (n == 0 && l == 0) g_done = 0;

    unsigned long long key = 0ull;
#pragma unroll
    for (int c = 0; c < CH; c++) {
        key |= ((unsigned long long)(targets[(n * CH + c) * LL + l] & 1)) << (CH - 1 - c);
    }
    skey[l] = (key << 8) | (unsigned long long)l;
    __syncthreads();

    for (int k = 2; k <= 256; k <<= 1) {
        for (int j = k >> 1; j > 0; j >>= 1) {
            int ixj = l ^ j;
            if (ixj > l) {
                unsigned long long a = skey[l], b = skey[ixj];
                bool up = ((l & k) == 0);
                if ((a > b) == up) { skey[l] = b; skey[ixj] = a; }
            }
            __syncthreads();
        }
    }

    unsigned long long kv = skey[l] >> 8;
    unsigned long long kvp = (l > 0) ? (skey[l - 1] >> 8) : 0ull;
    int head = (l == 0 || kv != kvp) ? 1 : 0;
    sscan[l] = head;
    __syncthreads();
    for (int off = 1; off < 256; off <<= 1) {
        int v = sscan[l];
        int w = (l >= off) ? sscan[l - off] : 0;
        __syncthreads();
        sscan[l] = v + w;
        __syncthreads();
    }
    const int u   = sscan[255];
    const int uid = sscan[l] - 1;
    const int orig = (int)(skey[l] & 255ull);
    int inv2 = uid + 1; if (inv2 == u) inv2 = 0;
    sinv[orig] = inv2;
    if (head) g_maskkeys[n * 256 + inv2] = kv;
    __syncthreads();

    int flag = (l > 0 && sinv[l] != sinv[l - 1]) ? 1 : 0;
    int myinv = sinv[l];
    sscan[l] = flag;
    __syncthreads();
    for (int off = 1; off < 256; off <<= 1) {
        int v = sscan[l];
        int w = (l >= off) ? sscan[l - off] : 0;
        __syncthreads();
        sscan[l] = v + w;
        __syncthreads();
    }
    if (flag) g_labels[n * 256 + (sscan[l] - 1)] = myinv;
    if (l == 0) g_tlen[n] = sscan[255];
}

// =====================================================================
// Kernel 2: emission table (verified exact)
// =====================================================================
__global__ void __launch_bounds__(128) k_emission(const float* __restrict__ lp) {
    const int n = blockIdx.y;
    const int t = blockIdx.x * 128 + threadIdx.x;

    __shared__ float maskf[CH * 256];
    for (int idx = threadIdx.x; idx < CH * 256; idx += 128) {
        int c = idx >> 8, j = idx & 255;
        unsigned long long mk = g_maskkeys[n * 256 + j];
        maskf[idx] = (float)((mk >> (CH - 1 - c)) & 1ull);
    }
    __syncthreads();
    if (t >= TT) return;

    const float* lp0 = lp + ((size_t)n * 2 + 0) * CH * TT;
    const float* lp1 = lp + ((size_t)n * 2 + 1) * CH * TT;

    unsigned long long d2[CH];
    float base = 0.0f;
    float blank = 0.0f;
#pragma unroll
    for (int c = 0; c < CH; c++) {
        float x0 = __ldg(lp0 + c * TT + t);
        float x1 = __ldg(lp1 + c * TT + t);
        if (c == 0) blank = x1;
        float dd = x1 - x0;
        base += x0;
        d2[c] = pk2(dd, dd);
    }

    float* out = g_em + ((size_t)n * TT + t) * 256;
    out[0] = blank * LOG2E;

    const unsigned long long b2 = pk2(base, base);
    for (int j8 = 0; j8 < 32; j8++) {
        unsigned long long acc0 = b2, acc1 = b2, acc2 = b2, acc3 = b2;
#pragma unroll
        for (int c = 0; c < CH; c++) {
            const float4* mp = (const float4*)(maskf + c * 256 + j8 * 8);
            float4 f0 = mp[0];
            float4 f1 = mp[1];
            ffma2(acc0, pk2(f0.x, f0.y), d2[c]);
            ffma2(acc1, pk2(f0.z, f0.w), d2[c]);
            ffma2(acc2, pk2(f1.x, f1.y), d2[c]);
            ffma2(acc3, pk2(f1.z, f1.w), d2[c]);
        }
        float vx, vy;
        int j = j8 * 8;
        up2(acc0, vx, vy);
        if (j > 0) out[j] = vx * LOG2E;
        out[j + 1] = vy * LOG2E;
        up2(acc1, vx, vy);
        out[j + 2] = vx * LOG2E; out[j + 3] = vy * LOG2E;
        up2(acc2, vx, vy);
        out[j + 4] = vx * LOG2E; out[j + 5] = vy * LOG2E;
        up2(acc3, vx, vy);
        out[j + 6] = vx * LOG2E; out[j + 7] = vy * LOG2E;
    }
}

// =====================================================================
// Kernel 3: CTC forward — halo wavefront with 2-STEP FUSED transitions.
// 11 warps; warp w covers pairs [24w, 24w+32), 8-pair halo -> 4 fused
// iterations (8 t-steps) per window between barriers.
// =====================================================================
__device__ __forceinline__ void stage_rows(float (*sEm)[256], const float* emn,
                                           int r0, int tid) {
    if (tid < 256) {
#pragma unroll
        for (int q = 0; q < 2; q++) {
            int c = tid * 2 + q;
            int r = r0 + (c >> 6);
            int off = (c & 63) * 4;
            if (r < TT) {
                uint32_t dst = (uint32_t)__cvta_generic_to_shared(&sEm[r & 31][off]);
                const float* src = emn + (size_t)r * 256 + off;
                asm volatile("cp.async.cg.shared.global [%0], [%1], 16;\n"
                             :: "r"(dst), "l"(src));
            }
        }
    }
    asm volatile("cp.async.commit_group;\n" ::: "memory");
}

__global__ void __launch_bounds__(352) k_ctc(float* __restrict__ d_out) {
    const int n = blockIdx.x;
    const int tid = threadIdx.x;
    const int w = tid >> 5;
    const int l = tid & 31;
    const int kp = 24 * w + l;

    __shared__ __align__(16) float sEm[32][256];
    __shared__ __align__(8)  float2 A2[2][288];

    const int tlen = g_tlen[n];
    const float* emn = g_em + (size_t)n * TT * 256;

    int labO = 0; bool skip = false;
    if (kp < tlen) {
        labO = g_labels[n * 256 + kp];
        if (kp >= 1) {
            int lm2 = g_labels[n * 256 + kp - 1];
            skip = (labO != 0) && (labO != lm2);
        }
    }
    const float skipSelO = (skip && tid != 0) ? POSF : NEGF;
    const float gSkip    = (skip && tid != 0) ? 1.0f : 0.0f;
    const int   labOL     = __shfl_up_sync(0xffffffffu, labO, 1);
    const float skipSelOL = __shfl_up_sync(0xffffffffu, skipSelO, 1);
    const float edge1 = (tid == 0) ? NEGF : POSF;   // kills dist-1 neighbors
    const float edge2 = (tid < 2)  ? NEGF : POSF;   // kills dist-2 neighbor

    for (int i = tid; i < 288; i += 352) {
        float2 v = make_float2(NEGF, NEGF);
        if (i == 0) {
            int lab0 = (tlen > 0) ? g_labels[n * 256] : 0;
            v = make_float2(__ldg(emn + 0), __ldg(emn + lab0));
        }
        A2[0][i] = v;
        A2[1][i] = make_float2(NEGF, NEGF);
    }

    stage_rows(sEm, emn, 1, tid);
    stage_rows(sEm, emn, 9, tid);

    int buf = 0;

// 2 fused time steps: (tt, tt+1)
#define FUSED2(tt)                                                          \
    do {                                                                    \
        const float* r0 = &sEm[(tt) & 31][0];                               \
        const float* r1 = &sEm[((tt) + 1) & 31][0];                         \
        float et0 = r0[0], etO = r0[labO], etOL = r0[labOL];                \
        float f0  = r1[0], fO  = r1[labO];                                  \
        float bO = __shfl_up_sync(0xffffffffu, aO, 1);                      \
        float bE = __shfl_up_sync(0xffffffffu, aE, 1);                      \
        float cO = __shfl_up_sync(0xffffffffu, aO, 2);                      \
        bO = fminf(bO, edge1);                                              \
        bE = fminf(bE, edge1);                                              \
        cO = fminf(fminf(cO, edge2), skipSelOL);                            \
        float A1  = aE + et0, A2t = bO + et0;                               \
        float B1  = bO + etOL, B2 = bE + etOL, B3 = cO + etOL;              \
        float C1  = aO + etO, C2 = aE + etO;                                \
        float C3  = fminf(bO, skipSelO) + etO;                              \
        float mAB = fmaxf(fmaxf(A1, A2t), fmaxf(fmaxf(B1, B2), B3));        \
        float mC  = fmaxf(fmaxf(C1, C2), C3);                               \
        float mO  = fmaxf(mC, mAB);                                         \
        float SA  = ex2f(A1 - mAB) + ex2f(A2t - mAB);                       \
        float SB  = ex2f(B1 - mAB) + ex2f(B2 - mAB) + ex2f(B3 - mAB);       \
        float SC  = ex2f(C1 - mO) + ex2f(C2 - mO) + ex2f(C3 - mO);          \
        float scl = ex2f(mAB - mO);                                         \
        float Osum = fmaf(fmaf(gSkip, SB, SA), scl, SC);                    \
        aE = mAB + lg2f(SA + SB) + f0;                                      \
        aO = mO  + lg2f(Osum) + fO;                                         \
    } while (0)

// single step at time tt
#define SINGLE1(tt)                                                         \
    do {                                                                    \
        const float* r0 = &sEm[(tt) & 31][0];                               \
        float emE = r0[0], emO = r0[labO];                                  \
        float aOp = __shfl_up_sync(0xffffffffu, aO, 1);                     \
        aOp = fminf(aOp, edge1);                                            \
        float cc = fminf(aOp, skipSelO);                                    \
        float mE = fmaxf(aE, aOp);                                          \
        float dE = fminf(aE, aOp) - mE;                                     \
        float hi = fmaxf(aO, aE), lo2 = fminf(aO, aE);                      \
        float mOs = fmaxf(hi, cc);                                          \
        float sec = fminf(hi, fmaxf(lo2, cc)) - mOs;                        \
        float th  = fminf(lo2, cc) - mOs;                                   \
        aE = mE  + lg2f(1.0f + ex2f(dE)) + emE;                             \
        aO = mOs + lg2f(1.0f + ex2f(sec) + ex2f(th)) + emO;                 \
    } while (0)

    for (int b = 0; b < 249; b++) {
        stage_rows(sEm, emn, 8 * b + 17, tid);
        asm volatile("cp.async.wait_group 2;\n" ::: "memory");
        __syncthreads();

        float2 a = A2[buf][kp];
        float aE = a.x, aO = a.y;
        const int t0 = 8 * b + 1;
#pragma unroll
        for (int i = 0; i < 4; i++) FUSED2(t0 + 2 * i);

        if (w == 0 || l >= 8) A2[buf ^ 1][kp] = make_float2(aE, aO);
        buf ^= 1;
    }

    // tail: t = 1993..1999 -> 3 fused iterations + 1 single step
    {
        asm volatile("cp.async.wait_group 0;\n" ::: "memory");
        __syncthreads();
        float2 a = A2[buf][kp];
        float aE = a.x, aO = a.y;
        FUSED2(1993);
        FUSED2(1995);
        FUSED2(1997);
        SINGLE1(1999);
        if (w == 0 || l >= 7) A2[buf ^ 1][kp] = make_float2(aE, aO);
        buf ^= 1;
    }
#undef FUSED2
#undef SINGLE1
    __syncthreads();

    if (tid == 0) {
        float ea = A2[buf][tlen].x;
        float eb = A2[buf][(tlen >= 1) ? tlen - 1 : 0].y;
        float m = fmaxf(ea, eb);
        float l2 = m + lg2f(ex2f(ea - m) + ex2f(eb - m));
        g_loss[n] = -l2 * LN2;
        __threadfence();
        unsigned int tk = atomicAdd(&g_done, 1u);
        if (tk == NB - 1) {
            volatile float* gl = g_loss;
            float s = 0.0f;
            for (int i = 0; i < NB; i++) s += gl[i];
            d_out[0] = s * (1.0f / (float)NB);
        }
    }
}

// =====================================================================
extern "C" void kernel_launch(void* const* d_in, const int* in_sizes, int n_in,
                              void* d_out, int out_size) {
    const float* lp = (const float*)d_in[0];
    const int*   tg = (const int*)d_in[1];
    if (n_in >= 2 && in_sizes[0] == NB * CH * LL) {
        lp = (const float*)d_in[1];
        tg = (const int*)d_in[0];
    }

    k_preprocess<<<NB, 256>>>(tg);
    dim3 g2((TT + 127) / 128, NB);
    k_emission<<<g2, 128>>>(lp);
    k_ctc<<<NB, 352>>>((float*)d_out);
}

// round 8
// speedup vs baseline: 1.1087x; 1.0599x over previous
#include <cuda_runtime.h>
#include <cstdint>
#include <cstddef>

#define CH   40
#define TT   2000
#define LL   256
#define NB   64
#define NEGF (-1.0e30f)
#define POSF (1.0e30f)
#define LOG2E 1.4426950408889634f
#define LN2   0.6931471805599453f

// lg2(1+u) ~ poly(x), x = u-1, u in [0,2]
#define D0 0.999835f
#define D1 0.721619f
#define D2 (-0.177414f)
#define D3 0.058070f
#define D4 (-0.029748f)
#define D5 0.0127536f

// ---------------- device scratch ----------------
__device__ unsigned long long g_maskkeys[NB * 256];
__device__ int   g_labels[NB * 256];
__device__ int   g_tlen[NB];
__device__ float g_em[(size_t)NB * TT * 256];
__device__ float g_loss[NB];
__device__ unsigned int g_done;

// ---------------- PTX helpers ----------------
__device__ __forceinline__ float ex2f(float x) {
    float r; asm("ex2.approx.ftz.f32 %0, %1;" : "=f"(r) : "f"(x)); return r;
}
__device__ __forceinline__ float lg2f(float x) {
    float r; asm("lg2.approx.ftz.f32 %0, %1;" : "=f"(r) : "f"(x)); return r;
}
__device__ __forceinline__ unsigned long long pk2(float x, float y) {
    unsigned long long r;
    asm("mov.b64 %0, {%1, %2};" : "=l"(r) : "f"(x), "f"(y));
    return r;
}
__device__ __forceinline__ void ffma2(unsigned long long &a, unsigned long long m, unsigned long long d) {
    asm("fma.rn.f32x2 %0, %1, %2, %3;" : "=l"(a) : "l"(m), "l"(d), "l"(a));
}
__device__ __forceinline__ void up2(unsigned long long v, float &x, float &y) {
    asm("mov.b64 {%0, %1}, %2;" : "=f"(x), "=f"(y) : "l"(v));
}

// =====================================================================
// Kernel 0: no-op (shifts ncu's captured-launch index onto k_ctc)
// =====================================================================
__global__ void k_nop() {}

// =====================================================================
// Kernel 1: preprocessing (verified exact)
// =====================================================================
__global__ void k_preprocess(const int* __restrict__ targets) {
    const int n = blockIdx.x;
    const int l = threadIdx.x;

    __shared__ unsigned long long skey[256];
    __shared__ int sscan[256];
    __shared__ int sinv[256];

    if (n == 0 && l == 0) g_done = 0;

    unsigned long long key = 0ull;
#pragma unroll
    for (int c = 0; c < CH; c++) {
        key |= ((unsigned long long)(targets[(n * CH + c) * LL + l] & 1)) << (CH - 1 - c);
    }
    skey[l] = (key << 8) | (unsigned long long)l;
    __syncthreads();

    for (int k = 2; k <= 256; k <<= 1) {
        for (int j = k >> 1; j > 0; j >>= 1) {
            int ixj = l ^ j;
            if (ixj > l) {
                unsigned long long a = skey[l], b = skey[ixj];
                bool up = ((l & k) == 0);
                if ((a > b) == up) { skey[l] = b; skey[ixj] = a; }
            }
            __syncthreads();
        }
    }

    unsigned long long kv = skey[l] >> 8;
    unsigned long long kvp = (l > 0) ? (skey[l - 1] >> 8) : 0ull;
    int head = (l == 0 || kv != kvp) ? 1 : 0;
    sscan[l] = head;
    __syncthreads();
    for (int off = 1; off < 256; off <<= 1) {
        int v = sscan[l];
        int w = (l >= off) ? sscan[l - off] : 0;
        __syncthreads();
        sscan[l] = v + w;
        __syncthreads();
    }
    const int u   = sscan[255];
    const int uid = sscan[l] - 1;
    const int orig = (int)(skey[l] & 255ull);
    int inv2 = uid + 1; if (inv2 == u) inv2 = 0;
    sinv[orig] = inv2;
    if (head) g_maskkeys[n * 256 + inv2] = kv;
    __syncthreads();

    int flag = (l > 0 && sinv[l] != sinv[l - 1]) ? 1 : 0;
    int myinv = sinv[l];
    sscan[l] = flag;
    __syncthreads();
    for (int off = 1; off < 256; off <<= 1) {
        int v = sscan[l];
        int w = (l >= off) ? sscan[l - off] : 0;
        __syncthreads();
        sscan[l] = v + w;
        __syncthreads();
    }
    if (flag) g_labels[n * 256 + (sscan[l] - 1)] = myinv;
    if (l == 0) g_tlen[n] = sscan[255];
}

// =====================================================================
// Kernel 2: emission table — pre-paired u64 masks (no pk2 movs),
// LOG2E folded into inputs, u64 stores.
// =====================================================================
__global__ void __launch_bounds__(128) k_emission(const float* __restrict__ lp) {
    const int n = blockIdx.y;
    const int t = blockIdx.x * 128 + threadIdx.x;

    __shared__ unsigned long long maskp[CH][128];   // [c][jpair] = (f(2jp), f(2jp+1))
    __shared__ unsigned long long skeys[256];

    for (int i = threadIdx.x; i < 256; i += 128) skeys[i] = g_maskkeys[n * 256 + i];
    __syncthreads();
    for (int idx = threadIdx.x; idx < CH * 128; idx += 128) {
        int c = idx >> 7, jp = idx & 127;
        unsigned long long k0 = skeys[2 * jp], k1 = skeys[2 * jp + 1];
        float f0 = (float)((k0 >> (CH - 1 - c)) & 1ull);
        float f1 = (float)((k1 >> (CH - 1 - c)) & 1ull);
        maskp[c][jp] = pk2(f0, f1);
    }
    __syncthreads();
    if (t >= TT) return;

    const float* lp0 = lp + ((size_t)n * 2 + 0) * CH * TT;
    const float* lp1 = lp + ((size_t)n * 2 + 1) * CH * TT;

    unsigned long long d2[CH];
    float base = 0.0f;
    float blankv = 0.0f;
#pragma unroll
    for (int c = 0; c < CH; c++) {
        float x0 = __ldg(lp0 + c * TT + t);
        float x1 = __ldg(lp1 + c * TT + t);
        if (c == 0) blankv = x1 * LOG2E;
        float dd = (x1 - x0) * LOG2E;
        base += x0;
        d2[c] = pk2(dd, dd);
    }
    base *= LOG2E;
    const unsigned long long b2 = pk2(base, base);

    unsigned long long* outp = (unsigned long long*)(g_em + ((size_t)n * TT + t) * 256);

    for (int j8 = 0; j8 < 32; j8++) {
        unsigned long long acc0 = b2, acc1 = b2, acc2 = b2, acc3 = b2;
#pragma unroll
        for (int c = 0; c < CH; c++) {
            const ulonglong2* mp = (const ulonglong2*)&maskp[c][j8 * 4];
            ulonglong2 ma = mp[0], mb = mp[1];
            ffma2(acc0, ma.x, d2[c]);
            ffma2(acc1, ma.y, d2[c]);
            ffma2(acc2, mb.x, d2[c]);
            ffma2(acc3, mb.y, d2[c]);
        }
        if (j8 == 0) {                      // j = 0 is the blank column
            float x, y;
            up2(acc0, x, y);
            acc0 = pk2(blankv, y);
        }
        outp[j8 * 4 + 0] = acc0;
        outp[j8 * 4 + 1] = acc1;
        outp[j8 * 4 + 2] = acc2;
        outp[j8 * 4 + 3] = acc3;
    }
}

// =====================================================================
// Kernel 3: CTC forward — 5 warps, 2 state-pairs (4 states) per thread.
// Halo wavefront: warp w covers pairs [48w, 48w+64), 8-lane (16-pair)
// overlap -> 8 steps per window, 1 barrier/window. In-thread neighbor
// for the upper pair (shfl count halved). Poly-lg2, fused mean.
// =====================================================================
__device__ __forceinline__ float lg2_poly(float u) {   // lg2(1+u), u in [0,2]
    float x = u - 1.0f;
    float x2 = x * x;
    float p = fmaf(D5, x, D4);
    float q = fmaf(D3, x, D2);
    float r = fmaf(D1, x, D0);
    p = fmaf(p, x2, q);
    return fmaf(p, x2, r);
}

__device__ __forceinline__ void stage_rows5(float (*sEm)[256], const float* emn,
                                            int r0, int tid) {
#pragma unroll
    for (int i = 0; i < 4; i++) {
        int c = tid + i * 160;
        if (c < 512) {
            int r = r0 + (c >> 6);
            int off = (c & 63) * 4;
            if (r < TT) {
                uint32_t dst = (uint32_t)__cvta_generic_to_shared(&sEm[r & 31][off]);
                const float* src = emn + (size_t)r * 256 + off;
                asm volatile("cp.async.cg.shared.global [%0], [%1], 16;\n"
                             :: "r"(dst), "l"(src));
            }
        }
    }
    asm volatile("cp.async.commit_group;\n" ::: "memory");
}

__global__ void __launch_bounds__(160) k_ctc(float* __restrict__ d_out) {
    const int n = blockIdx.x;
    const int tid = threadIdx.x;
    const int w = tid >> 5;
    const int l = tid & 31;
    const int q0 = 48 * w + 2 * l;      // lower pair
    const int q1 = q0 + 1;              // upper pair

    __shared__ __align__(16) float sEm[32][256];     // 32 KB ring
    __shared__ __align__(16) float4 EX[2][5][8];     // boundary exchange
    __shared__ __align__(8)  float2 AF[256];         // final alphas per pair

    const int tlen = g_tlen[n];
    const float* emn = g_em + (size_t)n * TT * 256;

    int lab0 = 0, lab1 = 0;
    float skip0 = NEGF, skip1 = NEGF;   // POSF = skip allowed (pass-through)
    if (q0 < tlen) {
        lab0 = g_labels[n * 256 + q0];
        if (q0 >= 1) {
            int lm = g_labels[n * 256 + q0 - 1];
            if (lab0 != 0 && lab0 != lm) skip0 = POSF;
        }
    }
    if (q1 < tlen) {
        lab1 = g_labels[n * 256 + q1];
        int lm = g_labels[n * 256 + q1 - 1];
        if (lab1 != 0 && lab1 != lm) skip1 = POSF;
    }
    const float edge1 = (tid == 0) ? NEGF : POSF;

    // t = 0 init
    float e0 = NEGF, o0 = NEGF, e1 = NEGF, o1 = NEGF;
    if (tid == 0) {
        e0 = __ldg(emn + 0);
        o0 = __ldg(emn + lab0);
    }

    stage_rows5(sEm, emn, 1, tid);
    stage_rows5(sEm, emn, 9, tid);

#define DO_STEP(tt)                                                         \
    do {                                                                    \
        const float* srow = &sEm[(tt) & 31][0];                             \
        float emE = srow[0];                                                \
        float em0 = srow[lab0];                                             \
        float em1 = srow[lab1];                                             \
        float aOp = __shfl_up_sync(0xffffffffu, o1, 1);                     \
        aOp = fminf(aOp, edge1);                                            \
        /* pair q0: preds (aOp, e0, o0) */                                  \
        float cc0 = fminf(aOp, skip0);                                      \
        float mE0 = fmaxf(e0, aOp);                                         \
        float dE0 = fminf(e0, aOp) - mE0;                                   \
        float hi0 = fmaxf(o0, e0), lo0 = fminf(o0, e0);                     \
        float mO0 = fmaxf(hi0, cc0);                                        \
        float se0 = fminf(hi0, fmaxf(lo0, cc0)) - mO0;                      \
        float th0 = fminf(lo0, cc0) - mO0;                                  \
        /* pair q1: preds (o0 old, e1, o1) */                               \
        float cc1 = fminf(o0, skip1);                                       \
        float mE1 = fmaxf(e1, o0);                                          \
        float dE1 = fminf(e1, o0) - mE1;                                    \
        float hi1 = fmaxf(o1, e1), lo1 = fminf(o1, e1);                     \
        float mO1 = fmaxf(hi1, cc1);                                        \
        float se1 = fminf(hi1, fmaxf(lo1, cc1)) - mO1;                      \
        float th1 = fminf(lo1, cc1) - mO1;                                  \
        float uE0 = ex2f(dE0);                                              \
        float uO0 = ex2f(se0) + ex2f(th0);                                  \
        float uE1 = ex2f(dE1);                                              \
        float uO1 = ex2f(se1) + ex2f(th1);                                  \
        e0 = (mE0 + emE) + lg2_poly(uE0);                                   \
        o0 = (mO0 + em0) + lg2_poly(uO0);                                   \
        e1 = (mE1 + emE) + lg2_poly(uE1);                                   \
        o1 = (mO1 + em1) + lg2_poly(uO1);                                   \
    } while (0)

    int buf = 0;
    for (int b = 0; b < 249; b++) {
        stage_rows5(sEm, emn, 8 * b + 17, tid);
        asm volatile("cp.async.wait_group 2;\n" ::: "memory");
        if (l >= 24) EX[buf][w][l - 24] = make_float4(e0, o0, e1, o1);
        __syncthreads();                 // rows-b visible + EX visible
        if (w > 0 && l < 8) {
            float4 v = EX[buf][w - 1][l];
            e0 = v.x; o0 = v.y; e1 = v.z; o1 = v.w;
        }
        buf ^= 1;

        const int t0 = 8 * b + 1;
#pragma unroll
        for (int s = 0; s < 8; s++) DO_STEP(t0 + s);
    }

    // tail: t = 1993..1999 (7 steps)
    {
        asm volatile("cp.async.wait_group 0;\n" ::: "memory");
        if (l >= 24) EX[buf][w][l - 24] = make_float4(e0, o0, e1, o1);
        __syncthreads();
        if (w > 0 && l < 8) {
            float4 v = EX[buf][w - 1][l];
            e0 = v.x; o0 = v.y; e1 = v.z; o1 = v.w;
        }
#pragma unroll
        for (int s = 0; s < 7; s++) DO_STEP(1993 + s);
    }
#undef DO_STEP

    // collect final alphas (valid lanes: warp0 all; others l >= 7)
    if (w == 0 || l >= 7) {
        AF[q0] = make_float2(e0, o0);
        AF[q1] = make_float2(e1, o1);
    }
    __syncthreads();

    if (tid == 0) {
        float ea = AF[tlen].x;                          // alpha[2*tlen]
        float eb = AF[(tlen >= 1) ? tlen - 1 : 0].y;    // alpha[2*tlen-1]
        float m = fmaxf(ea, eb);
        float l2 = m + lg2f(ex2f(ea - m) + ex2f(eb - m));
        g_loss[n] = -l2 * LN2;
        __threadfence();
        unsigned int tk = atomicAdd(&g_done, 1u);
        if (tk == NB - 1) {
            __threadfence();
            volatile float* gl = g_loss;
            float s = 0.0f;
            for (int i = 0; i < NB; i++) s += gl[i];
            d_out[0] = s * (1.0f / (float)NB);
        }
    }
}

// =====================================================================
extern "C" void kernel_launch(void* const* d_in, const int* in_sizes, int n_in,
                              void* d_out, int out_size) {
    const float* lp = (const float*)d_in[0];
    const int*   tg = (const int*)d_in[1];
    if (n_in >= 2 && in_sizes[0] == NB * CH * LL) {
        lp = (const float*)d_in[1];
        tg = (const int*)d_in[0];
    }

    k_nop<<<1, 32>>>();
    k_preprocess<<<NB, 256>>>(tg);
    dim3 g2((TT + 127) / 128, NB);
    k_emission<<<g2, 128>>>(lp);
    k_ctc<<<NB, 160>>>((float*)d_out);
}

// round 9
// speedup vs baseline: 1.3871x; 1.2511x over previous
#include <cuda_runtime.h>
#include <cstdint>
#include <cstddef>

#define CH   40
#define TT   2000
#define LL   256
#define NB   64
#define NEGF (-1.0e30f)
#define POSF (1.0e30f)
#define LOG2E 1.4426950408889634f
#define LN2   0.6931471805599453f

// lg2(1+u) ~ poly(x), x = u-1, u in [0,2]
#define D0 0.999835f
#define D1 0.721619f
#define D2 (-0.177414f)
#define D3 0.058070f
#define D4 (-0.029748f)
#define D5 0.0127536f

// ---------------- device scratch ----------------
__device__ unsigned long long g_maskkeys[NB * 256];
__device__ int   g_labels[NB * 256];
__device__ int   g_tlen[NB];
__device__ float g_em[(size_t)NB * TT * 256];
__device__ float g_loss[NB];
__device__ unsigned int g_done;

// ---------------- PTX helpers ----------------
__device__ __forceinline__ float ex2f(float x) {
    float r; asm("ex2.approx.ftz.f32 %0, %1;" : "=f"(r) : "f"(x)); return r;
}
__device__ __forceinline__ float lg2f(float x) {
    float r; asm("lg2.approx.ftz.f32 %0, %1;" : "=f"(r) : "f"(x)); return r;
}
__device__ __forceinline__ unsigned long long pk2(float x, float y) {
    unsigned long long r;
    asm("mov.b64 %0, {%1, %2};" : "=l"(r) : "f"(x), "f"(y));
    return r;
}
__device__ __forceinline__ void ffma2(unsigned long long &a, unsigned long long m, unsigned long long d) {
    asm("fma.rn.f32x2 %0, %1, %2, %3;" : "=l"(a) : "l"(m), "l"(d), "l"(a));
}
__device__ __forceinline__ void up2(unsigned long long v, float &x, float &y) {
    asm("mov.b64 {%0, %1}, %2;" : "=f"(x), "=f"(y) : "l"(v));
}

// =====================================================================
// Kernel 0: no-op (keeps ncu capture index on k_ctc)
// =====================================================================
__global__ void k_nop() {}

// =====================================================================
// Kernel 1: preprocessing (verified exact)
// =====================================================================
__global__ void k_preprocess(const int* __restrict__ targets) {
    const int n = blockIdx.x;
    const int l = threadIdx.x;

    __shared__ unsigned long long skey[256];
    __shared__ int sscan[256];
    __shared__ int sinv[256];

    if (n == 0 && l == 0) g_done = 0;

    unsigned long long key = 0ull;
#pragma unroll
    for (int c = 0; c < CH; c++) {
        key |= ((unsigned long long)(targets[(n * CH + c) * LL + l] & 1)) << (CH - 1 - c);
    }
    skey[l] = (key << 8) | (unsigned long long)l;
    __syncthreads();

    for (int k = 2; k <= 256; k <<= 1) {
        for (int j = k >> 1; j > 0; j >>= 1) {
            int ixj = l ^ j;
            if (ixj > l) {
                unsigned long long a = skey[l], b = skey[ixj];
                bool up = ((l & k) == 0);
                if ((a > b) == up) { skey[l] = b; skey[ixj] = a; }
            }
            __syncthreads();
        }
    }

    unsigned long long kv = skey[l] >> 8;
    unsigned long long kvp = (l > 0) ? (skey[l - 1] >> 8) : 0ull;
    int head = (l == 0 || kv != kvp) ? 1 : 0;
    sscan[l] = head;
    __syncthreads();
    for (int off = 1; off < 256; off <<= 1) {
        int v = sscan[l];
        int w = (l >= off) ? sscan[l - off] : 0;
        __syncthreads();
        sscan[l] = v + w;
        __syncthreads();
    }
    const int u   = sscan[255];
    const int uid = sscan[l] - 1;
    const int orig = (int)(skey[l] & 255ull);
    int inv2 = uid + 1; if (inv2 == u) inv2 = 0;
    sinv[orig] = inv2;
    if (head) g_maskkeys[n * 256 + inv2] = kv;
    __syncthreads();

    int flag = (l > 0 && sinv[l] != sinv[l - 1]) ? 1 : 0;
    int myinv = sinv[l];
    sscan[l] = flag;
    __syncthreads();
    for (int off = 1; off < 256; off <<= 1) {
        int v = sscan[l];
        int w = (l >= off) ? sscan[l - off] : 0;
        __syncthreads();
        sscan[l] = v + w;
        __syncthreads();
    }
    if (flag) g_labels[n * 256 + (sscan[l] - 1)] = myinv;
    if (l == 0) g_tlen[n] = sscan[255];
}

// =====================================================================
// Kernel 2: emission table v2 — thread = j column, 32-t tile per block.
// d2/base/blank staged in shared (broadcast reads); warp stores are
// 32 consecutive j's per t -> fully coalesced.
// =====================================================================
#define TTILE 32
__global__ void __launch_bounds__(256) k_emission(const float* __restrict__ lp) {
    const int n  = blockIdx.y;
    const int t0 = blockIdx.x * TTILE;
    const int j  = threadIdx.x;          // 0..255

    __shared__ __align__(16) float d2f[CH][TTILE];  // (lp1-lp0)*LOG2E
    __shared__ float sbase[TTILE];                  // sum_c lp0 * LOG2E
    __shared__ float sblank[TTILE];                 // lp1[c=0] * LOG2E

    const float* lp0 = lp + ((size_t)n * 2 + 0) * CH * TT;
    const float* lp1 = lp + ((size_t)n * 2 + 1) * CH * TT;

    // stage d2f: 1280 entries, 5 passes of 256 threads
#pragma unroll
    for (int it = 0; it < 5; it++) {
        int idx = it * 256 + j;
        int c = idx >> 5;          // /32
        int tt = idx & 31;
        int t = t0 + tt;
        float v = 0.0f;
        if (t < TT) {
            float x0 = __ldg(lp0 + c * TT + t);
            float x1 = __ldg(lp1 + c * TT + t);
            v = (x1 - x0) * LOG2E;
        }
        d2f[c][tt] = v;
    }
    // base + blank (threads 0..31, coalesced per c)
    if (j < TTILE) {
        int t = t0 + j;
        float b = 0.0f, bl = 0.0f;
        if (t < TT) {
#pragma unroll
            for (int c = 0; c < CH; c++) b += __ldg(lp0 + c * TT + t);
            bl = __ldg(lp1 + t);
        }
        sbase[j]  = b * LOG2E;
        sblank[j] = bl * LOG2E;
    }
    __syncthreads();

    const unsigned long long mk = g_maskkeys[n * 256 + j];

    unsigned long long acc[TTILE / 2];
    const unsigned long long* basep = (const unsigned long long*)sbase;
#pragma unroll
    for (int tp = 0; tp < TTILE / 2; tp++) acc[tp] = basep[tp];

#pragma unroll 10
    for (int c = 0; c < CH; c++) {
        float m = (float)((mk >> (CH - 1 - c)) & 1ull);
        unsigned long long mm = pk2(m, m);
        const unsigned long long* drow = (const unsigned long long*)&d2f[c][0];
#pragma unroll
        for (int tp = 0; tp < TTILE / 2; tp++) {
            ffma2(acc[tp], mm, drow[tp]);
        }
    }

    // coalesced stores: warp writes 32 consecutive j for each t
    float* outb = g_em + ((size_t)n * TT + t0) * 256 + j;
#pragma unroll
    for (int tp = 0; tp < TTILE / 2; tp++) {
        float v0, v1;
        up2(acc[tp], v0, v1);
        int te = 2 * tp, to = 2 * tp + 1;
        if (j == 0) { v0 = sblank[te]; v1 = sblank[to]; }
        if (t0 + te < TT) outb[(size_t)te * 256] = v0;
        if (t0 + to < TT) outb[(size_t)to * 256] = v1;
    }
}

// =====================================================================
// Kernel 3: CTC forward — 5 warps, 2 state-pairs per thread, halo
// windows. Odd LSE via MUFU lg2, even via poly. Fused mean.
// =====================================================================
__device__ __forceinline__ float lg2_poly(float u) {   // lg2(1+u), u in [0,2]
    float x = u - 1.0f;
    float x2 = x * x;
    float p = fmaf(D5, x, D4);
    float q = fmaf(D3, x, D2);
    float r = fmaf(D1, x, D0);
    p = fmaf(p, x2, q);
    return fmaf(p, x2, r);
}

__device__ __forceinline__ void stage_rows5(float (*sEm)[256], const float* emn,
                                            int r0, int tid) {
#pragma unroll
    for (int i = 0; i < 4; i++) {
        int c = tid + i * 160;
        if (c < 512) {
            int r = r0 + (c >> 6);
            int off = (c & 63) * 4;
            if (r < TT) {
                uint32_t dst = (uint32_t)__cvta_generic_to_shared(&sEm[r & 31][off]);
                const float* src = emn + (size_t)r * 256 + off;
                asm volatile("cp.async.cg.shared.global [%0], [%1], 16;\n"
                             :: "r"(dst), "l"(src));
            }
        }
    }
    asm volatile("cp.async.commit_group;\n" ::: "memory");
}

__global__ void __launch_bounds__(160) k_ctc(float* __restrict__ d_out) {
    const int n = blockIdx.x;
    const int tid = threadIdx.x;
    const int w = tid >> 5;
    const int l = tid & 31;
    const int q0 = 48 * w + 2 * l;
    const int q1 = q0 + 1;

    __shared__ __align__(16) float sEm[32][256];
    __shared__ __align__(16) float4 EX[2][5][8];
    __shared__ __align__(8)  float2 AF[256];

    const int tlen = g_tlen[n];
    const float* emn = g_em + (size_t)n * TT * 256;

    int lab0 = 0, lab1 = 0;
    float skip0 = NEGF, skip1 = NEGF;
    if (q0 < tlen) {
        lab0 = g_labels[n * 256 + q0];
        if (q0 >= 1) {
            int lm = g_labels[n * 256 + q0 - 1];
            if (lab0 != 0 && lab0 != lm) skip0 = POSF;
        }
    }
    if (q1 < tlen) {
        lab1 = g_labels[n * 256 + q1];
        int lm = g_labels[n * 256 + q1 - 1];
        if (lab1 != 0 && lab1 != lm) skip1 = POSF;
    }
    const float edge1 = (tid == 0) ? NEGF : POSF;

    float e0 = NEGF, o0 = NEGF, e1 = NEGF, o1 = NEGF;
    if (tid == 0) {
        e0 = __ldg(emn + 0);
        o0 = __ldg(emn + lab0);
    }

    stage_rows5(sEm, emn, 1, tid);
    stage_rows5(sEm, emn, 9, tid);

#define DO_STEP(tt)                                                         \
    do {                                                                    \
        const float* srow = &sEm[(tt) & 31][0];                             \
        float emE = srow[0];                                                \
        float em0 = srow[lab0];                                             \
        float em1 = srow[lab1];                                             \
        float aOp = __shfl_up_sync(0xffffffffu, o1, 1);                     \
        aOp = fminf(aOp, edge1);                                            \
        float cc0 = fminf(aOp, skip0);                                      \
        float mE0 = fmaxf(e0, aOp);                                         \
        float dE0 = fminf(e0, aOp) - mE0;                                   \
        float hi0 = fmaxf(o0, e0), lo0 = fminf(o0, e0);                     \
        float mO0 = fmaxf(hi0, cc0);                                        \
        float se0 = fminf(hi0, fmaxf(lo0, cc0)) - mO0;                      \
        float th0 = fminf(lo0, cc0) - mO0;                                  \
        float cc1 = fminf(o0, skip1);                                       \
        float mE1 = fmaxf(e1, o0);                                          \
        float dE1 = fminf(e1, o0) - mE1;                                    \
        float hi1 = fmaxf(o1, e1), lo1 = fminf(o1, e1);                     \
        float mO1 = fmaxf(hi1, cc1);                                        \
        float se1 = fminf(hi1, fmaxf(lo1, cc1)) - mO1;                      \
        float th1 = fminf(lo1, cc1) - mO1;                                  \
        float uE0 = ex2f(dE0);                                              \
        float uO0 = 1.0f + ex2f(se0) + ex2f(th0);                           \
        float uE1 = ex2f(dE1);                                              \
        float uO1 = 1.0f + ex2f(se1) + ex2f(th1);                           \
        e0 = (mE0 + emE) + lg2_poly(uE0);                                   \
        o0 = (mO0 + em0) + lg2f(uO0);                                       \
        e1 = (mE1 + emE) + lg2_poly(uE1);                                   \
        o1 = (mO1 + em1) + lg2f(uO1);                                       \
    } while (0)

    int buf = 0;
    for (int b = 0; b < 249; b++) {
        stage_rows5(sEm, emn, 8 * b + 17, tid);
        asm volatile("cp.async.wait_group 2;\n" ::: "memory");
        if (l >= 24) EX[buf][w][l - 24] = make_float4(e0, o0, e1, o1);
        __syncthreads();
        if (w > 0 && l < 8) {
            float4 v = EX[buf][w - 1][l];
            e0 = v.x; o0 = v.y; e1 = v.z; o1 = v.w;
        }
        buf ^= 1;

        const int t0 = 8 * b + 1;
#pragma unroll
        for (int s = 0; s < 8; s++) DO_STEP(t0 + s);
    }

    {
        asm volatile("cp.async.wait_group 0;\n" ::: "memory");
        if (l >= 24) EX[buf][w][l - 24] = make_float4(e0, o0, e1, o1);
        __syncthreads();
        if (w > 0 && l < 8) {
            float4 v = EX[buf][w - 1][l];
            e0 = v.x; o0 = v.y; e1 = v.z; o1 = v.w;
        }
#pragma unroll
        for (int s = 0; s < 7; s++) DO_STEP(1993 + s);
    }
#undef DO_STEP

    if (w == 0 || l >= 7) {
        AF[q0] = make_float2(e0, o0);
        AF[q1] = make_float2(e1, o1);
    }
    __syncthreads();

    if (tid == 0) {
        float ea = AF[tlen].x;
        float eb = AF[(tlen >= 1) ? tlen - 1 : 0].y;
        float m = fmaxf(ea, eb);
        float l2 = m + lg2f(ex2f(ea - m) + ex2f(eb - m));
        g_loss[n] = -l2 * LN2;
        __threadfence();
        unsigned int tk = atomicAdd(&g_done, 1u);
        if (tk == NB - 1) {
            __threadfence();
            volatile float* gl = g_loss;
            float s = 0.0f;
            for (int i = 0; i < NB; i++) s += gl[i];
            d_out[0] = s * (1.0f / (float)NB);
        }
    }
}

// =====================================================================
extern "C" void kernel_launch(void* const* d_in, const int* in_sizes, int n_in,
                              void* d_out, int out_size) {
    const float* lp = (const float*)d_in[0];
    const int*   tg = (const int*)d_in[1];
    if (n_in >= 2 && in_sizes[0] == NB * CH * LL) {
        lp = (const float*)d_in[1];
        tg = (const int*)d_in[0];
    }

    k_nop<<<1, 32>>>();
    k_preprocess<<<NB, 256>>>(tg);
    dim3 g2((TT + TTILE - 1) / TTILE, NB);
    k_emission<<<g2, 256>>>(lp);
    k_ctc<<<NB, 160>>>((float*)d_out);
}